// round 1
// baseline (speedup 1.0000x reference)
#include <cuda_runtime.h>

// Problem constants (fixed shapes from reference)
#define CB 4          // batch
#define CT 8192       // time
#define CD 1024       // D_IN
#define CH 1024       // D_H
#define CO 1024       // D_OUT
#define CM (CB*CT)    // 32768 rows
#define NCHUNK 32
#define CHUNK (CT/NCHUNK)   // 256
#define LN_EPS 1e-5f

// ---------------- scratch (device globals; no allocation allowed) -------------
__device__ float g_ih[(size_t)CM*CH];    // ih_raw -> beta -> local-scan h
__device__ float g_gate[(size_t)CM*CH];  // gate_raw -> alpha -> prefix-prod
__device__ float g_hn[(size_t)CM*CH];    // normalized h
__device__ float g_cA[CB*NCHUNK*CH];
__device__ float g_cB[CB*NCHUNK*CH];
__device__ float g_pref[CB*NCHUNK*CH];

// ---------------- SGEMM: C[m][n] = sum_k A[m*K+k] * B[n*K+k] (+bias[n]) -------
// A: MxK row-major, B: NxK row-major (both K-contiguous). 128x128 tile, BK=8,
// 256 threads, 8x8 per-thread microtile.
template<bool BIAS>
__global__ __launch_bounds__(256) void sgemm_tn(
    const float* __restrict__ A, const float* __restrict__ B,
    const float* __restrict__ bias, float* __restrict__ C,
    int M, int N, int K)
{
    __shared__ float As[8][128];
    __shared__ float Bs[8][128];

    const int tid = threadIdx.x;
    const int m0 = blockIdx.y * 128;
    const int n0 = blockIdx.x * 128;

    const int lr = tid >> 1;          // 0..127: tile row to load
    const int lc = (tid & 1) * 4;     // 0 or 4: k offset

    const float* Ap = A + (size_t)(m0 + lr) * K + lc;
    const float* Bp = B + (size_t)(n0 + lr) * K + lc;

    const int ty = tid >> 4;          // 0..15
    const int tx = tid & 15;          // 0..15

    float acc[8][8];
#pragma unroll
    for (int i = 0; i < 8; i++)
#pragma unroll
        for (int j = 0; j < 8; j++) acc[i][j] = 0.f;

    for (int k0 = 0; k0 < K; k0 += 8) {
        float4 av = *reinterpret_cast<const float4*>(Ap + k0);
        float4 bv = *reinterpret_cast<const float4*>(Bp + k0);
        As[lc+0][lr] = av.x; As[lc+1][lr] = av.y;
        As[lc+2][lr] = av.z; As[lc+3][lr] = av.w;
        Bs[lc+0][lr] = bv.x; Bs[lc+1][lr] = bv.y;
        Bs[lc+2][lr] = bv.z; Bs[lc+3][lr] = bv.w;
        __syncthreads();

#pragma unroll
        for (int kk = 0; kk < 8; kk++) {
            float4 a0 = *reinterpret_cast<const float4*>(&As[kk][ty*8]);
            float4 a1 = *reinterpret_cast<const float4*>(&As[kk][ty*8+4]);
            float4 b0 = *reinterpret_cast<const float4*>(&Bs[kk][tx*8]);
            float4 b1 = *reinterpret_cast<const float4*>(&Bs[kk][tx*8+4]);
            float ar[8] = {a0.x,a0.y,a0.z,a0.w,a1.x,a1.y,a1.z,a1.w};
            float br[8] = {b0.x,b0.y,b0.z,b0.w,b1.x,b1.y,b1.z,b1.w};
#pragma unroll
            for (int i = 0; i < 8; i++)
#pragma unroll
                for (int j = 0; j < 8; j++)
                    acc[i][j] += ar[i] * br[j];
        }
        __syncthreads();
    }

#pragma unroll
    for (int i = 0; i < 8; i++) {
        const int m = m0 + ty*8 + i;
        float* Cp = C + (size_t)m * N + n0 + tx*8;
        float4 v0, v1;
        float out[8];
#pragma unroll
        for (int j = 0; j < 8; j++) {
            float v = acc[i][j];
            if (BIAS) v += bias[n0 + tx*8 + j];
            out[j] = v;
        }
        v0.x=out[0]; v0.y=out[1]; v0.z=out[2]; v0.w=out[3];
        v1.x=out[4]; v1.y=out[5]; v1.z=out[6]; v1.w=out[7];
        *reinterpret_cast<float4*>(Cp)     = v0;
        *reinterpret_cast<float4*>(Cp + 4) = v1;
    }
}

// ---------- elementwise: gate=sigmoid(gt+b_g); beta=gate*(ih+b_ih); ----------
// ----------             alpha=(1-gate)*exp(log_a)  (in-place)       ----------
__global__ __launch_bounds__(256) void make_ab(
    float* __restrict__ ih, float* __restrict__ gt,
    const float* __restrict__ b_ih, const float* __restrict__ b_g,
    const float* __restrict__ log_a)
{
    size_t i4 = (size_t)blockIdx.x * blockDim.x + threadIdx.x;
    size_t i = i4 * 4;
    int h = (int)(i % CH);
    float4 iv = *reinterpret_cast<float4*>(ih + i);
    float4 gv = *reinterpret_cast<float4*>(gt + i);
    float ivv[4] = {iv.x, iv.y, iv.z, iv.w};
    float gvv[4] = {gv.x, gv.y, gv.z, gv.w};
    float bo[4], ao[4];
#pragma unroll
    for (int c = 0; c < 4; c++) {
        float gate = 1.f / (1.f + __expf(-(gvv[c] + b_g[h + c])));
        bo[c] = gate * (ivv[c] + b_ih[h + c]);
        ao[c] = (1.f - gate) * __expf(log_a[h + c]);
    }
    float4 bw = {bo[0], bo[1], bo[2], bo[3]};
    float4 aw = {ao[0], ao[1], ao[2], ao[3]};
    *reinterpret_cast<float4*>(ih + i) = bw;
    *reinterpret_cast<float4*>(gt + i) = aw;
}

// ---------------- pass A: local scan per (b,h,chunk), in-place ----------------
// alpha[t] <- running product P_t ; beta[t] <- local h_t (scan from 0)
__global__ __launch_bounds__(256) void scan_local(
    float* __restrict__ alpha, float* __restrict__ beta,
    float* __restrict__ cA, float* __restrict__ cB)
{
    int idx = blockIdx.x * blockDim.x + threadIdx.x;  // B*H*NCHUNK threads
    int h = idx % CH;
    int c = (idx / CH) % NCHUNK;
    int b = idx / (CH * NCHUNK);
    size_t base = ((size_t)b * CT + (size_t)c * CHUNK) * CH + h;
    float p = 1.f, hl = 0.f;
#pragma unroll 4
    for (int t = 0; t < CHUNK; t++) {
        size_t o = base + (size_t)t * CH;
        float a = alpha[o];
        float bt = beta[o];
        hl = fmaf(a, hl, bt);
        p *= a;
        alpha[o] = p;
        beta[o] = hl;
    }
    cA[((size_t)b * NCHUNK + c) * CH + h] = p;
    cB[((size_t)b * NCHUNK + c) * CH + h] = hl;
}

// ---------------- pass B: scan across chunk summaries per (b,h) ---------------
__global__ __launch_bounds__(256) void scan_carry(
    const float* __restrict__ cA, const float* __restrict__ cB,
    float* __restrict__ pref)
{
    int idx = blockIdx.x * blockDim.x + threadIdx.x;  // B*H threads
    int h = idx % CH;
    int b = idx / CH;
    float run = 0.f;
#pragma unroll
    for (int c = 0; c < NCHUNK; c++) {
        size_t o = ((size_t)b * NCHUNK + c) * CH + h;
        pref[o] = run;
        run = fmaf(cA[o], run, cB[o]);
    }
}

// ------------- pass C: fixup h = h_local + P*carry, fused LayerNorm -----------
__global__ __launch_bounds__(256) void fix_ln(
    const float* __restrict__ P, const float* __restrict__ HL,
    const float* __restrict__ pref,
    const float* __restrict__ lng, const float* __restrict__ lnb,
    float* __restrict__ hn)
{
    __shared__ float sred[16];
    const int row = blockIdx.x;        // 0..CM-1
    const int b = row / CT;
    const int t = row % CT;
    const int c = t / CHUNK;
    const size_t base = (size_t)row * CH;
    const float* prow = pref + ((size_t)b * NCHUNK + c) * CH;
    const int h = threadIdx.x * 4;

    float4 p4  = *reinterpret_cast<const float4*>(P + base + h);
    float4 hl4 = *reinterpret_cast<const float4*>(HL + base + h);
    float4 pr4 = *reinterpret_cast<const float4*>(prow + h);
    float v[4];
    v[0] = fmaf(p4.x, pr4.x, hl4.x);
    v[1] = fmaf(p4.y, pr4.y, hl4.y);
    v[2] = fmaf(p4.z, pr4.z, hl4.z);
    v[3] = fmaf(p4.w, pr4.w, hl4.w);

    float s = v[0] + v[1] + v[2] + v[3];
    float ss = v[0]*v[0] + v[1]*v[1] + v[2]*v[2] + v[3]*v[3];
#pragma unroll
    for (int off = 16; off > 0; off >>= 1) {
        s  += __shfl_xor_sync(0xffffffffu, s,  off);
        ss += __shfl_xor_sync(0xffffffffu, ss, off);
    }
    const int warp = threadIdx.x >> 5, lane = threadIdx.x & 31;
    if (lane == 0) { sred[warp] = s; sred[8 + warp] = ss; }
    __syncthreads();
    if (threadIdx.x < 32) {
        float a  = (lane < 8) ? sred[lane]     : 0.f;
        float b2 = (lane < 8) ? sred[8 + lane] : 0.f;
#pragma unroll
        for (int off = 4; off > 0; off >>= 1) {
            a  += __shfl_xor_sync(0xffffffffu, a,  off);
            b2 += __shfl_xor_sync(0xffffffffu, b2, off);
        }
        if (lane == 0) { sred[0] = a; sred[1] = b2; }
    }
    __syncthreads();
    const float mu  = sred[0] * (1.f / CH);
    const float var = sred[1] * (1.f / CH) - mu * mu;
    const float inv = rsqrtf(var + LN_EPS);

    float4 g4 = *reinterpret_cast<const float4*>(lng + h);
    float4 b4 = *reinterpret_cast<const float4*>(lnb + h);
    float4 o4;
    o4.x = (v[0] - mu) * inv * g4.x + b4.x;
    o4.y = (v[1] - mu) * inv * g4.y + b4.y;
    o4.z = (v[2] - mu) * inv * g4.z + b4.z;
    o4.w = (v[3] - mu) * inv * g4.w + b4.w;
    *reinterpret_cast<float4*>(hn + base + h) = o4;
}

// --------------------------------- launcher ----------------------------------
extern "C" void kernel_launch(void* const* d_in, const int* in_sizes, int n_in,
                              void* d_out, int out_size)
{
    const float* x      = (const float*)d_in[0];
    const float* W_ih   = (const float*)d_in[1];
    const float* b_ih   = (const float*)d_in[2];
    const float* log_a  = (const float*)d_in[3];
    const float* W_gate = (const float*)d_in[4];
    const float* b_gate = (const float*)d_in[5];
    const float* W_out  = (const float*)d_in[6];
    const float* b_out  = (const float*)d_in[7];
    const float* ln_g   = (const float*)d_in[8];
    const float* ln_b   = (const float*)d_in[9];
    float* out = (float*)d_out;

    float *ih, *gt, *hn, *cA, *cB, *pref;
    cudaGetSymbolAddress((void**)&ih,   g_ih);
    cudaGetSymbolAddress((void**)&gt,   g_gate);
    cudaGetSymbolAddress((void**)&hn,   g_hn);
    cudaGetSymbolAddress((void**)&cA,   g_cA);
    cudaGetSymbolAddress((void**)&cB,   g_cB);
    cudaGetSymbolAddress((void**)&pref, g_pref);

    dim3 blk(256);
    dim3 gg(CH / 128, CM / 128);

    sgemm_tn<false><<<gg, blk>>>(x, W_ih,   nullptr, ih, CM, CH, CD);
    sgemm_tn<false><<<gg, blk>>>(x, W_gate, nullptr, gt, CM, CH, CD);

    make_ab<<<(CM * (size_t)CH / 4) / 256, 256>>>(ih, gt, b_ih, b_gate, log_a);

    scan_local<<<(CB * CH * NCHUNK) / 256, 256>>>(gt, ih, cA, cB);
    scan_carry<<<(CB * CH) / 256, 256>>>(cA, cB, pref);
    fix_ln<<<CM, 256>>>(gt, ih, pref, ln_g, ln_b, hn);

    sgemm_tn<true><<<dim3(CO / 128, CM / 128), blk>>>(hn, W_out, b_out, out, CM, CO, CH);
}

// round 2
// speedup vs baseline: 1.5522x; 1.5522x over previous
#include <cuda_runtime.h>
#include <cuda_bf16.h>
#include <cstdint>

// Problem constants (fixed shapes from reference)
#define CB 4          // batch
#define CT 8192       // time
#define CD 1024       // D_IN
#define CH 1024       // D_H
#define CO 1024       // D_OUT
#define CM (CB*CT)    // 32768 rows
#define NCHUNK 32
#define CHUNK (CT/NCHUNK)   // 256
#define LN_EPS 1e-5f

// ---------------- scratch (device globals; no allocation allowed) -------------
__device__ __nv_bfloat16 g_xhi[(size_t)CM*CD];
__device__ __nv_bfloat16 g_xlo[(size_t)CM*CD];
__device__ __nv_bfloat16 g_w1hi[(size_t)CH*CD], g_w1lo[(size_t)CH*CD];
__device__ __nv_bfloat16 g_w2hi[(size_t)CH*CD], g_w2lo[(size_t)CH*CD];
__device__ __nv_bfloat16 g_w3hi[(size_t)CO*CH], g_w3lo[(size_t)CO*CH];
__device__ float g_ih[(size_t)CM*CH];    // ih_raw -> local-scan h
__device__ float g_gate[(size_t)CM*CH];  // gate_raw -> prefix-prod
__device__ __nv_bfloat16 g_hnhi[(size_t)CM*CH];
__device__ __nv_bfloat16 g_hnlo[(size_t)CM*CH];
__device__ float g_cA[CB*NCHUNK*CH];
__device__ float g_cB[CB*NCHUNK*CH];
__device__ float g_pref[CB*NCHUNK*CH];

// ------------------------- fp32 -> bf16 hi/lo split ---------------------------
__global__ __launch_bounds__(256) void split32(
    const float* __restrict__ src,
    __nv_bfloat16* __restrict__ hi, __nv_bfloat16* __restrict__ lo)
{
    size_t i = ((size_t)blockIdx.x * 256 + threadIdx.x) * 4;
    float4 v = *reinterpret_cast<const float4*>(src + i);
    float vv[4] = {v.x, v.y, v.z, v.w};
    __nv_bfloat16 h[4], l[4];
#pragma unroll
    for (int c = 0; c < 4; c++) {
        h[c] = __float2bfloat16(vv[c]);
        l[c] = __float2bfloat16(vv[c] - __bfloat162float(h[c]));
    }
    __nv_bfloat162* ph = reinterpret_cast<__nv_bfloat162*>(hi + i);
    __nv_bfloat162* pl = reinterpret_cast<__nv_bfloat162*>(lo + i);
    ph[0] = __nv_bfloat162(h[0], h[1]);
    ph[1] = __nv_bfloat162(h[2], h[3]);
    pl[0] = __nv_bfloat162(l[0], l[1]);
    pl[1] = __nv_bfloat162(l[2], l[3]);
}

// ---------------------- bf16-split tensor-core GEMM ---------------------------
// C[m][n] = sum_k A[m][k]*B[n][k] (+bias[n]), A: MxK, B: NxK, both K-contig.
// Split: A=Ahi+Alo, B=Bhi+Blo; acc += Ahi*Bhi + Ahi*Blo + Alo*Bhi (fp32 acc).
// 128x128 tile, BK=32, 256 threads (8 warps as 2m x 4n), mma.m16n8k16.

#define RS 40                  // smem row stride in bf16 (80B; conflict-free)
#define PARTB (128*RS*2)       // bytes per operand part per stage = 10240
#define STAGEB (PARTB*4)       // Ahi|Alo|Bhi|Blo = 40960 per stage

__device__ __forceinline__ void cp16(uint32_t s, const void* g) {
    asm volatile("cp.async.cg.shared.global [%0], [%1], 16;" :: "r"(s), "l"(g));
}

#define MMA_BF16(d, a, b) \
    asm volatile("mma.sync.aligned.m16n8k16.row.col.f32.bf16.bf16.f32 " \
        "{%0,%1,%2,%3}, {%4,%5,%6,%7}, {%8,%9}, {%0,%1,%2,%3};" \
        : "+f"(d[0]), "+f"(d[1]), "+f"(d[2]), "+f"(d[3]) \
        : "r"(a[0]), "r"(a[1]), "r"(a[2]), "r"(a[3]), "r"(b[0]), "r"(b[1]))

__global__ __launch_bounds__(256) void gemm_bf16x2(
    const __nv_bfloat16* __restrict__ Ahi, const __nv_bfloat16* __restrict__ Alo,
    const __nv_bfloat16* __restrict__ Bhi, const __nv_bfloat16* __restrict__ Blo,
    const float* __restrict__ bias, float* __restrict__ C,
    int M, int N, int K)
{
    extern __shared__ char smem[];
    const uint32_t smem_u32 = (uint32_t)__cvta_generic_to_shared(smem);

    const int tid = threadIdx.x;
    const int m0 = blockIdx.y * 128;
    const int n0 = blockIdx.x * 128;

    const int wid = tid >> 5, lane = tid & 31;
    const int wm = wid >> 2;       // 0..1
    const int wn = wid & 3;        // 0..3
    const int g  = lane >> 2;      // 0..7
    const int tq = lane & 3;       // 0..3

    const __nv_bfloat16* srcs[4] = {
        Ahi + (size_t)m0 * K, Alo + (size_t)m0 * K,
        Bhi + (size_t)n0 * K, Blo + (size_t)n0 * K };

    // issue one stage of cp.async loads
    auto issue = [&](int st, int k0) {
        uint32_t sbase = smem_u32 + st * STAGEB;
#pragma unroll
        for (int p = 0; p < 4; p++) {
#pragma unroll
            for (int rep = 0; rep < 2; rep++) {
                int idx = tid + rep * 256;      // 0..511
                int r = idx >> 2, c = idx & 3;  // row 0..127, 16B-chunk 0..3
                const void* gp = srcs[p] + (size_t)r * K + k0 + c * 8;
                cp16(sbase + p * PARTB + r * (RS * 2) + c * 16, gp);
            }
        }
        asm volatile("cp.async.commit_group;");
    };

    float acc[4][4][4];
#pragma unroll
    for (int i = 0; i < 4; i++)
#pragma unroll
        for (int j = 0; j < 4; j++)
#pragma unroll
            for (int c = 0; c < 4; c++) acc[i][j][c] = 0.f;

    issue(0, 0);

    const int NIT = K / 32;
    for (int it = 0; it < NIT; ++it) {
        asm volatile("cp.async.wait_group 0;");
        __syncthreads();
        if (it + 1 < NIT) issue((it + 1) & 1, (it + 1) * 32);

        const __nv_bfloat16* S    = (const __nv_bfloat16*)(smem + (it & 1) * STAGEB);
        const __nv_bfloat16* sAhi = S;
        const __nv_bfloat16* sAlo = S + 128 * RS;
        const __nv_bfloat16* sBhi = S + 2 * 128 * RS;
        const __nv_bfloat16* sBlo = S + 3 * 128 * RS;

#pragma unroll
        for (int ks = 0; ks < 2; ks++) {
            const int c0 = ks * 16 + tq * 2;
            const int c1 = c0 + 8;
            uint32_t ahi[4][4], alo[4][4], bhi[4][2], blo[4][2];
#pragma unroll
            for (int i = 0; i < 4; i++) {
                int r0 = wm * 64 + i * 16 + g, r1 = r0 + 8;
                ahi[i][0] = *(const uint32_t*)(sAhi + r0 * RS + c0);
                ahi[i][1] = *(const uint32_t*)(sAhi + r1 * RS + c0);
                ahi[i][2] = *(const uint32_t*)(sAhi + r0 * RS + c1);
                ahi[i][3] = *(const uint32_t*)(sAhi + r1 * RS + c1);
                alo[i][0] = *(const uint32_t*)(sAlo + r0 * RS + c0);
                alo[i][1] = *(const uint32_t*)(sAlo + r1 * RS + c0);
                alo[i][2] = *(const uint32_t*)(sAlo + r0 * RS + c1);
                alo[i][3] = *(const uint32_t*)(sAlo + r1 * RS + c1);
            }
#pragma unroll
            for (int j = 0; j < 4; j++) {
                int n = wn * 32 + j * 8 + g;
                bhi[j][0] = *(const uint32_t*)(sBhi + n * RS + c0);
                bhi[j][1] = *(const uint32_t*)(sBhi + n * RS + c1);
                blo[j][0] = *(const uint32_t*)(sBlo + n * RS + c0);
                blo[j][1] = *(const uint32_t*)(sBlo + n * RS + c1);
            }
#pragma unroll
            for (int i = 0; i < 4; i++)
#pragma unroll
                for (int j = 0; j < 4; j++) {
                    MMA_BF16(acc[i][j], ahi[i], bhi[j]);
                    MMA_BF16(acc[i][j], ahi[i], blo[j]);
                    MMA_BF16(acc[i][j], alo[i], bhi[j]);
                }
        }
        __syncthreads();
    }

    // epilogue
#pragma unroll
    for (int i = 0; i < 4; i++) {
        const int m = m0 + wm * 64 + i * 16 + g;
#pragma unroll
        for (int j = 0; j < 4; j++) {
            const int n = n0 + wn * 32 + j * 8 + tq * 2;
            float b0 = 0.f, b1 = 0.f;
            if (bias) { b0 = bias[n]; b1 = bias[n + 1]; }
            float2 v0 = { acc[i][j][0] + b0, acc[i][j][1] + b1 };
            float2 v1 = { acc[i][j][2] + b0, acc[i][j][3] + b1 };
            *reinterpret_cast<float2*>(C + (size_t)m * N + n)       = v0;
            *reinterpret_cast<float2*>(C + (size_t)(m + 8) * N + n) = v1;
        }
    }
}

// ---- pass A (fused): gate/alpha/beta from raw GEMM outputs + local scan ------
// gate_arr holds raw gate pre-activation -> becomes running product P
// ih_arr holds raw ih -> becomes local h
__global__ __launch_bounds__(256) void scan_local(
    float* __restrict__ ih_arr, float* __restrict__ gate_arr,
    const float* __restrict__ b_ih, const float* __restrict__ b_g,
    const float* __restrict__ log_a,
    float* __restrict__ cA, float* __restrict__ cB)
{
    int idx = blockIdx.x * blockDim.x + threadIdx.x;  // B*H*NCHUNK threads
    int h = idx % CH;
    int c = (idx / CH) % NCHUNK;
    int b = idx / (CH * NCHUNK);
    const float bg = b_g[h], bi = b_ih[h], ea = __expf(log_a[h]);
    size_t base = ((size_t)b * CT + (size_t)c * CHUNK) * CH + h;
    float p = 1.f, hl = 0.f;
#pragma unroll 4
    for (int t = 0; t < CHUNK; t++) {
        size_t o = base + (size_t)t * CH;
        float graw = gate_arr[o];
        float iraw = ih_arr[o];
        float gate = 1.f / (1.f + __expf(-(graw + bg)));
        float beta = gate * (iraw + bi);
        float a = (1.f - gate) * ea;
        hl = fmaf(a, hl, beta);
        p *= a;
        gate_arr[o] = p;
        ih_arr[o] = hl;
    }
    cA[((size_t)b * NCHUNK + c) * CH + h] = p;
    cB[((size_t)b * NCHUNK + c) * CH + h] = hl;
}

// ---------------- pass B: scan across chunk summaries per (b,h) ---------------
__global__ __launch_bounds__(256) void scan_carry(
    const float* __restrict__ cA, const float* __restrict__ cB,
    float* __restrict__ pref)
{
    int idx = blockIdx.x * blockDim.x + threadIdx.x;  // B*H threads
    int h = idx % CH;
    int b = idx / CH;
    float run = 0.f;
#pragma unroll
    for (int c = 0; c < NCHUNK; c++) {
        size_t o = ((size_t)b * NCHUNK + c) * CH + h;
        pref[o] = run;
        run = fmaf(cA[o], run, cB[o]);
    }
}

// ------- pass C: fixup h = h_local + P*carry, fused LayerNorm -> bf16 hi/lo ----
__global__ __launch_bounds__(256) void fix_ln(
    const float* __restrict__ P, const float* __restrict__ HL,
    const float* __restrict__ pref,
    const float* __restrict__ lng, const float* __restrict__ lnb,
    __nv_bfloat16* __restrict__ hnhi, __nv_bfloat16* __restrict__ hnlo)
{
    __shared__ float sred[16];
    const int row = blockIdx.x;        // 0..CM-1
    const int b = row / CT;
    const int t = row % CT;
    const int c = t / CHUNK;
    const size_t base = (size_t)row * CH;
    const float* prow = pref + ((size_t)b * NCHUNK + c) * CH;
    const int h = threadIdx.x * 4;

    float4 p4  = *reinterpret_cast<const float4*>(P + base + h);
    float4 hl4 = *reinterpret_cast<const float4*>(HL + base + h);
    float4 pr4 = *reinterpret_cast<const float4*>(prow + h);
    float v[4];
    v[0] = fmaf(p4.x, pr4.x, hl4.x);
    v[1] = fmaf(p4.y, pr4.y, hl4.y);
    v[2] = fmaf(p4.z, pr4.z, hl4.z);
    v[3] = fmaf(p4.w, pr4.w, hl4.w);

    float s = v[0] + v[1] + v[2] + v[3];
    float ss = v[0]*v[0] + v[1]*v[1] + v[2]*v[2] + v[3]*v[3];
#pragma unroll
    for (int off = 16; off > 0; off >>= 1) {
        s  += __shfl_xor_sync(0xffffffffu, s,  off);
        ss += __shfl_xor_sync(0xffffffffu, ss, off);
    }
    const int warp = threadIdx.x >> 5, lane = threadIdx.x & 31;
    if (lane == 0) { sred[warp] = s; sred[8 + warp] = ss; }
    __syncthreads();
    if (threadIdx.x < 32) {
        float a  = (lane < 8) ? sred[lane]     : 0.f;
        float b2 = (lane < 8) ? sred[8 + lane] : 0.f;
#pragma unroll
        for (int off = 4; off > 0; off >>= 1) {
            a  += __shfl_xor_sync(0xffffffffu, a,  off);
            b2 += __shfl_xor_sync(0xffffffffu, b2, off);
        }
        if (lane == 0) { sred[0] = a; sred[1] = b2; }
    }
    __syncthreads();
    const float mu  = sred[0] * (1.f / CH);
    const float var = sred[1] * (1.f / CH) - mu * mu;
    const float inv = rsqrtf(var + LN_EPS);

    float4 g4 = *reinterpret_cast<const float4*>(lng + h);
    float4 b4 = *reinterpret_cast<const float4*>(lnb + h);
    float o[4];
    o[0] = (v[0] - mu) * inv * g4.x + b4.x;
    o[1] = (v[1] - mu) * inv * g4.y + b4.y;
    o[2] = (v[2] - mu) * inv * g4.z + b4.z;
    o[3] = (v[3] - mu) * inv * g4.w + b4.w;

    __nv_bfloat16 hi[4], lo[4];
#pragma unroll
    for (int k = 0; k < 4; k++) {
        hi[k] = __float2bfloat16(o[k]);
        lo[k] = __float2bfloat16(o[k] - __bfloat162float(hi[k]));
    }
    __nv_bfloat162* ph = reinterpret_cast<__nv_bfloat162*>(hnhi + base + h);
    __nv_bfloat162* pl = reinterpret_cast<__nv_bfloat162*>(hnlo + base + h);
    ph[0] = __nv_bfloat162(hi[0], hi[1]);
    ph[1] = __nv_bfloat162(hi[2], hi[3]);
    pl[0] = __nv_bfloat162(lo[0], lo[1]);
    pl[1] = __nv_bfloat162(lo[2], lo[3]);
}

// --------------------------------- launcher ----------------------------------
extern "C" void kernel_launch(void* const* d_in, const int* in_sizes, int n_in,
                              void* d_out, int out_size)
{
    const float* x      = (const float*)d_in[0];
    const float* W_ih   = (const float*)d_in[1];
    const float* b_ih   = (const float*)d_in[2];
    const float* log_a  = (const float*)d_in[3];
    const float* W_gate = (const float*)d_in[4];
    const float* b_gate = (const float*)d_in[5];
    const float* W_out  = (const float*)d_in[6];
    const float* b_out  = (const float*)d_in[7];
    const float* ln_g   = (const float*)d_in[8];
    const float* ln_b   = (const float*)d_in[9];
    float* out = (float*)d_out;

    __nv_bfloat16 *xhi, *xlo, *w1hi, *w1lo, *w2hi, *w2lo, *w3hi, *w3lo, *hnhi, *hnlo;
    float *ih, *gt, *cA, *cB, *pref;
    cudaGetSymbolAddress((void**)&xhi,  g_xhi);
    cudaGetSymbolAddress((void**)&xlo,  g_xlo);
    cudaGetSymbolAddress((void**)&w1hi, g_w1hi);
    cudaGetSymbolAddress((void**)&w1lo, g_w1lo);
    cudaGetSymbolAddress((void**)&w2hi, g_w2hi);
    cudaGetSymbolAddress((void**)&w2lo, g_w2lo);
    cudaGetSymbolAddress((void**)&w3hi, g_w3hi);
    cudaGetSymbolAddress((void**)&w3lo, g_w3lo);
    cudaGetSymbolAddress((void**)&hnhi, g_hnhi);
    cudaGetSymbolAddress((void**)&hnlo, g_hnlo);
    cudaGetSymbolAddress((void**)&ih,   g_ih);
    cudaGetSymbolAddress((void**)&gt,   g_gate);
    cudaGetSymbolAddress((void**)&cA,   g_cA);
    cudaGetSymbolAddress((void**)&cB,   g_cB);
    cudaGetSymbolAddress((void**)&pref, g_pref);

    cudaFuncSetAttribute(gemm_bf16x2,
                         cudaFuncAttributeMaxDynamicSharedMemorySize, 2 * STAGEB);

    // splits
    split32<<<(size_t)CM * CD / 4 / 256, 256>>>(x,      xhi,  xlo);
    split32<<<(size_t)CH * CD / 4 / 256, 256>>>(W_ih,   w1hi, w1lo);
    split32<<<(size_t)CH * CD / 4 / 256, 256>>>(W_gate, w2hi, w2lo);
    split32<<<(size_t)CO * CH / 4 / 256, 256>>>(W_out,  w3hi, w3lo);

    // input GEMMs
    dim3 g1(CH / 128, CM / 128);
    gemm_bf16x2<<<g1, 256, 2 * STAGEB>>>(xhi, xlo, w1hi, w1lo, nullptr, ih, CM, CH, CD);
    gemm_bf16x2<<<g1, 256, 2 * STAGEB>>>(xhi, xlo, w2hi, w2lo, nullptr, gt, CM, CH, CD);

    // fused elementwise + chunked scan
    scan_local<<<(CB * CH * NCHUNK) / 256, 256>>>(ih, gt, b_ih, b_gate, log_a, cA, cB);
    scan_carry<<<(CB * CH) / 256, 256>>>(cA, cB, pref);
    fix_ln<<<CM, 256>>>(gt, ih, pref, ln_g, ln_b, hnhi, hnlo);

    // output GEMM
    dim3 g3(CO / 128, CM / 128);
    gemm_bf16x2<<<g3, 256, 2 * STAGEB>>>(hnhi, hnlo, w3hi, w3lo, b_out, out, CM, CO, CH);
}

// round 4
// speedup vs baseline: 2.4699x; 1.5913x over previous
#include <cuda_runtime.h>
#include <cuda_bf16.h>
#include <cstdint>

// Problem constants (fixed shapes from reference)
#define CB 4
#define CT 8192
#define CD 1024
#define CH 1024
#define CO 1024
#define CM (CB*CT)    // 32768 rows
#define NCHUNK 32
#define CHUNK (CT/NCHUNK)   // 256
#define LN_EPS 1e-5f

// ---------------- scratch (device globals; no allocation allowed) -------------
__device__ __nv_bfloat16 g_xhi[(size_t)CM*CD];
__device__ __nv_bfloat16 g_xlo[(size_t)CM*CD];
__device__ __nv_bfloat16 g_w1hi[(size_t)CH*CD], g_w1lo[(size_t)CH*CD];
__device__ __nv_bfloat16 g_w2hi[(size_t)CH*CD], g_w2lo[(size_t)CH*CD];
__device__ __nv_bfloat16 g_w3hi[(size_t)CO*CH], g_w3lo[(size_t)CO*CH];
__device__ float g_ih[(size_t)CM*CH];
__device__ float g_gate[(size_t)CM*CH];
__device__ __nv_bfloat16 g_hnhi[(size_t)CM*CH];
__device__ __nv_bfloat16 g_hnlo[(size_t)CM*CH];
__device__ float g_cA[CB*NCHUNK*CH];
__device__ float g_cB[CB*NCHUNK*CH];
__device__ float g_pref[CB*NCHUNK*CH];

// ------------------------------ helpers ---------------------------------------
__device__ __forceinline__ uint32_t s2u(const void* p) {
    return (uint32_t)__cvta_generic_to_shared(p);
}
__device__ __forceinline__ void cp16(uint32_t s, const void* g) {
    asm volatile("cp.async.cg.shared.global [%0], [%1], 16;" :: "r"(s), "l"(g));
}
#define CP_COMMIT() asm volatile("cp.async.commit_group;" ::: "memory")

__device__ __forceinline__ void ldsm4(uint32_t* r, uint32_t addr) {
    asm volatile("ldmatrix.sync.aligned.m8n8.x4.shared.b16 {%0,%1,%2,%3}, [%4];"
        : "=r"(r[0]), "=r"(r[1]), "=r"(r[2]), "=r"(r[3]) : "r"(addr));
}

#define MMA_BF16(d, a, b) \
    asm volatile("mma.sync.aligned.m16n8k16.row.col.f32.bf16.bf16.f32 " \
        "{%0,%1,%2,%3}, {%4,%5,%6,%7}, {%8,%9}, {%0,%1,%2,%3};" \
        : "+f"(d[0]), "+f"(d[1]), "+f"(d[2]), "+f"(d[3]) \
        : "r"(a[0]), "r"(a[1]), "r"(a[2]), "r"(a[3]), "r"(b[0]), "r"(b[1]))

// ------------------------- fp32 -> bf16 hi/lo split ---------------------------
__global__ __launch_bounds__(256) void split32(
    const float* __restrict__ src,
    __nv_bfloat16* __restrict__ hi, __nv_bfloat16* __restrict__ lo)
{
    size_t i = ((size_t)blockIdx.x * 256 + threadIdx.x) * 4;
    float4 v = *reinterpret_cast<const float4*>(src + i);
    float vv[4] = {v.x, v.y, v.z, v.w};
    __nv_bfloat16 h[4], l[4];
#pragma unroll
    for (int c = 0; c < 4; c++) {
        h[c] = __float2bfloat16(vv[c]);
        l[c] = __float2bfloat16(vv[c] - __bfloat162float(h[c]));
    }
    __nv_bfloat162* ph = reinterpret_cast<__nv_bfloat162*>(hi + i);
    __nv_bfloat162* pl = reinterpret_cast<__nv_bfloat162*>(lo + i);
    ph[0] = __nv_bfloat162(h[0], h[1]);
    ph[1] = __nv_bfloat162(h[2], h[3]);
    pl[0] = __nv_bfloat162(l[0], l[1]);
    pl[1] = __nv_bfloat162(l[2], l[3]);
}

// ---------------------- bf16-split tensor-core GEMM ---------------------------
// C[m][n] = sum_k A[m][k]*B[n][k] (+bias[n]); A: MxK, B: NxK, K-contig.
// 128x128 tile, BK=64, 3-stage cp.async, ldmatrix.x4 fragment loads,
// XOR-swizzled 128B smem rows (conflict-free), mma.m16n8k16 bf16 3-pass split.

#define PART_B 16384               // 128 rows x 128B (64 bf16)
#define STAGE_B (4*PART_B)         // Ahi|Alo|Bhi|Blo = 64KB per stage
#define NSTAGE 3
#define DYN_B (NSTAGE*STAGE_B + 1024)

__global__ __launch_bounds__(256, 1) void gemm_bf16x2(
    const __nv_bfloat16* __restrict__ Ahi, const __nv_bfloat16* __restrict__ Alo,
    const __nv_bfloat16* __restrict__ Bhi, const __nv_bfloat16* __restrict__ Blo,
    const float* __restrict__ bias, float* __restrict__ C,
    int M, int N, int K)
{
    extern __shared__ char dyn[];
    const uint32_t tile = (s2u(dyn) + 127u) & ~127u;

    const int tid = threadIdx.x;
    const int m0 = blockIdx.y * 128;
    const int n0 = blockIdx.x * 128;

    const int wid = tid >> 5, lane = tid & 31;
    const int wm = wid >> 2;       // 0..1
    const int wn = wid & 3;        // 0..3

    const __nv_bfloat16* srcs[4] = {
        Ahi + (size_t)m0 * K, Alo + (size_t)m0 * K,
        Bhi + (size_t)n0 * K, Blo + (size_t)n0 * K };

    // cp.async: thread t -> row r = t>>1, chunks (t&1)*4 .. +3 (16B each)
    const int lr = tid >> 1;
    const int lc0 = (tid & 1) * 4;
    const int lsw = lr & 7;

    auto issue = [&](int s) {
        uint32_t sb = tile + (uint32_t)(s % NSTAGE) * STAGE_B;
        int k0 = s * 64;
#pragma unroll
        for (int p = 0; p < 4; p++) {
            const __nv_bfloat16* g = srcs[p] + (size_t)lr * K + k0 + lc0 * 8;
            uint32_t base = sb + p * PART_B + lr * 128;
#pragma unroll
            for (int c = 0; c < 4; c++)
                cp16(base + (((lc0 + c) ^ lsw) << 4), g + c * 8);
        }
        CP_COMMIT();
    };

    // ldmatrix address precomputation (row part; chunk xor applied per ks)
    // A frags: row = wm*64 + i*16 + (lane&15), chunk half = lane>>4
    const int arow = wm * 64 + (lane & 15);
    const int ahalf = lane >> 4;
    const int asw = arow & 7;
    // B frags: row = wn*32 + q*16 + ((lane>>4)<<3) + (lane&7), half = (lane>>3)&1
    const int brow = wn * 32 + ((lane >> 4) << 3) + (lane & 7);
    const int bhalf = (lane >> 3) & 1;
    const int bsw = brow & 7;

    float acc[4][4][4];
#pragma unroll
    for (int i = 0; i < 4; i++)
#pragma unroll
        for (int j = 0; j < 4; j++)
#pragma unroll
            for (int c = 0; c < 4; c++) acc[i][j][c] = 0.f;

    issue(0); issue(1); issue(2);

    const int NIT = K / 64;
    for (int it = 0; it < NIT; ++it) {
        if (it + 2 < NIT)      asm volatile("cp.async.wait_group 2;" ::: "memory");
        else if (it + 1 < NIT) asm volatile("cp.async.wait_group 1;" ::: "memory");
        else                   asm volatile("cp.async.wait_group 0;" ::: "memory");
        __syncthreads();

        uint32_t sb = tile + (uint32_t)(it % NSTAGE) * STAGE_B;
        uint32_t aAhi = sb              + arow * 128;
        uint32_t aAlo = sb +     PART_B + arow * 128;
        uint32_t aBhi = sb + 2 * PART_B + brow * 128;
        uint32_t aBlo = sb + 3 * PART_B + brow * 128;

#pragma unroll
        for (int ks = 0; ks < 4; ks++) {
            const int ac = (2 * ks + ahalf) ^ asw;
            const int bc = (2 * ks + bhalf) ^ bsw;
            uint32_t ahi[4][4], alo[4][4], bhi[4][2], blo[4][2];
#pragma unroll
            for (int i = 0; i < 4; i++) {
                ldsm4(ahi[i], aAhi + i * (16 * 128) + (ac << 4));
                ldsm4(alo[i], aAlo + i * (16 * 128) + (ac << 4));
            }
#pragma unroll
            for (int q = 0; q < 2; q++) {
                uint32_t rb[4];
                ldsm4(rb, aBhi + q * (16 * 128) + (bc << 4));
                bhi[q*2+0][0] = rb[0]; bhi[q*2+0][1] = rb[1];
                bhi[q*2+1][0] = rb[2]; bhi[q*2+1][1] = rb[3];
                ldsm4(rb, aBlo + q * (16 * 128) + (bc << 4));
                blo[q*2+0][0] = rb[0]; blo[q*2+0][1] = rb[1];
                blo[q*2+1][0] = rb[2]; blo[q*2+1][1] = rb[3];
            }
#pragma unroll
            for (int i = 0; i < 4; i++)
#pragma unroll
                for (int j = 0; j < 4; j++) {
                    MMA_BF16(acc[i][j], ahi[i], bhi[j]);
                    MMA_BF16(acc[i][j], ahi[i], blo[j]);
                    MMA_BF16(acc[i][j], alo[i], bhi[j]);
                }
        }
        __syncthreads();
        if (it + NSTAGE < NIT) issue(it + NSTAGE);
    }

    // epilogue: lane l -> rows +l/4 (+8), cols + 2*(l%4)
    const int g = lane >> 2, tq = lane & 3;
#pragma unroll
    for (int i = 0; i < 4; i++) {
        const int m = m0 + wm * 64 + i * 16 + g;
#pragma unroll
        for (int j = 0; j < 4; j++) {
            const int n = n0 + wn * 32 + j * 8 + tq * 2;
            float b0 = 0.f, b1 = 0.f;
            if (bias) { b0 = bias[n]; b1 = bias[n + 1]; }
            float2 v0 = { acc[i][j][0] + b0, acc[i][j][1] + b1 };
            float2 v1 = { acc[i][j][2] + b0, acc[i][j][3] + b1 };
            *reinterpret_cast<float2*>(C + (size_t)m * N + n)       = v0;
            *reinterpret_cast<float2*>(C + (size_t)(m + 8) * N + n) = v1;
        }
    }
}

// ---- pass A (fused): gate/alpha/beta from raw GEMM outputs + local scan ------
__global__ __launch_bounds__(256) void scan_local(
    float* __restrict__ ih_arr, float* __restrict__ gate_arr,
    const float* __restrict__ b_ih, const float* __restrict__ b_g,
    const float* __restrict__ log_a,
    float* __restrict__ cA, float* __restrict__ cB)
{
    int idx = blockIdx.x * blockDim.x + threadIdx.x;  // B*H*NCHUNK threads
    int h = idx % CH;
    int c = (idx / CH) % NCHUNK;
    int b = idx / (CH * NCHUNK);
    const float bg = b_g[h], bi = b_ih[h], ea = __expf(log_a[h]);
    size_t base = ((size_t)b * CT + (size_t)c * CHUNK) * CH + h;
    float p = 1.f, hl = 0.f;
#pragma unroll 4
    for (int t = 0; t < CHUNK; t++) {
        size_t o = base + (size_t)t * CH;
        float graw = gate_arr[o];
        float iraw = ih_arr[o];
        float gate = 1.f / (1.f + __expf(-(graw + bg)));
        float beta = gate * (iraw + bi);
        float a = (1.f - gate) * ea;
        hl = fmaf(a, hl, beta);
        p *= a;
        gate_arr[o] = p;
        ih_arr[o] = hl;
    }
    cA[((size_t)b * NCHUNK + c) * CH + h] = p;
    cB[((size_t)b * NCHUNK + c) * CH + h] = hl;
}

// ---------------- pass B: scan across chunk summaries per (b,h) ---------------
__global__ __launch_bounds__(256) void scan_carry(
    const float* __restrict__ cA, const float* __restrict__ cB,
    float* __restrict__ pref)
{
    int idx = blockIdx.x * blockDim.x + threadIdx.x;  // B*H threads
    int h = idx % CH;
    int b = idx / CH;
    float run = 0.f;
#pragma unroll
    for (int c = 0; c < NCHUNK; c++) {
        size_t o = ((size_t)b * NCHUNK + c) * CH + h;
        pref[o] = run;
        run = fmaf(cA[o], run, cB[o]);
    }
}

// ------- pass C: fixup h = h_local + P*carry, fused LayerNorm -> bf16 hi/lo ----
__global__ __launch_bounds__(256) void fix_ln(
    const float* __restrict__ P, const float* __restrict__ HL,
    const float* __restrict__ pref,
    const float* __restrict__ lng, const float* __restrict__ lnb,
    __nv_bfloat16* __restrict__ hnhi, __nv_bfloat16* __restrict__ hnlo)
{
    __shared__ float sred[16];
    const int row = blockIdx.x;
    const int b = row / CT;
    const int t = row % CT;
    const int c = t / CHUNK;
    const size_t base = (size_t)row * CH;
    const float* prow = pref + ((size_t)b * NCHUNK + c) * CH;
    const int h = threadIdx.x * 4;

    float4 p4  = *reinterpret_cast<const float4*>(P + base + h);
    float4 hl4 = *reinterpret_cast<const float4*>(HL + base + h);
    float4 pr4 = *reinterpret_cast<const float4*>(prow + h);
    float v[4];
    v[0] = fmaf(p4.x, pr4.x, hl4.x);
    v[1] = fmaf(p4.y, pr4.y, hl4.y);
    v[2] = fmaf(p4.z, pr4.z, hl4.z);
    v[3] = fmaf(p4.w, pr4.w, hl4.w);

    float s = v[0] + v[1] + v[2] + v[3];
    float ss = v[0]*v[0] + v[1]*v[1] + v[2]*v[2] + v[3]*v[3];
#pragma unroll
    for (int off = 16; off > 0; off >>= 1) {
        s  += __shfl_xor_sync(0xffffffffu, s,  off);
        ss += __shfl_xor_sync(0xffffffffu, ss, off);
    }
    const int warp = threadIdx.x >> 5, lane = threadIdx.x & 31;
    if (lane == 0) { sred[warp] = s; sred[8 + warp] = ss; }
    __syncthreads();
    if (threadIdx.x < 32) {
        float a  = (lane < 8) ? sred[lane]     : 0.f;
        float b2 = (lane < 8) ? sred[8 + lane] : 0.f;
#pragma unroll
        for (int off = 4; off > 0; off >>= 1) {
            a  += __shfl_xor_sync(0xffffffffu, a,  off);
            b2 += __shfl_xor_sync(0xffffffffu, b2, off);
        }
        if (lane == 0) { sred[0] = a; sred[1] = b2; }
    }
    __syncthreads();
    const float mu  = sred[0] * (1.f / CH);
    const float var = sred[1] * (1.f / CH) - mu * mu;
    const float inv = rsqrtf(var + LN_EPS);

    float4 g4 = *reinterpret_cast<const float4*>(lng + h);
    float4 b4 = *reinterpret_cast<const float4*>(lnb + h);
    float o[4];
    o[0] = (v[0] - mu) * inv * g4.x + b4.x;
    o[1] = (v[1] - mu) * inv * g4.y + b4.y;
    o[2] = (v[2] - mu) * inv * g4.z + b4.z;
    o[3] = (v[3] - mu) * inv * g4.w + b4.w;

    __nv_bfloat16 hi[4], lo[4];
#pragma unroll
    for (int k = 0; k < 4; k++) {
        hi[k] = __float2bfloat16(o[k]);
        lo[k] = __float2bfloat16(o[k] - __bfloat162float(hi[k]));
    }
    __nv_bfloat162* phh = reinterpret_cast<__nv_bfloat162*>(hnhi + base + h);
    __nv_bfloat162* pll = reinterpret_cast<__nv_bfloat162*>(hnlo + base + h);
    phh[0] = __nv_bfloat162(hi[0], hi[1]);
    phh[1] = __nv_bfloat162(hi[2], hi[3]);
    pll[0] = __nv_bfloat162(lo[0], lo[1]);
    pll[1] = __nv_bfloat162(lo[2], lo[3]);
}

// --------------------------------- launcher ----------------------------------
extern "C" void kernel_launch(void* const* d_in, const int* in_sizes, int n_in,
                              void* d_out, int out_size)
{
    const float* x      = (const float*)d_in[0];
    const float* W_ih   = (const float*)d_in[1];
    const float* b_ih   = (const float*)d_in[2];
    const float* log_a  = (const float*)d_in[3];
    const float* W_gate = (const float*)d_in[4];
    const float* b_gate = (const float*)d_in[5];
    const float* W_out  = (const float*)d_in[6];
    const float* b_out  = (const float*)d_in[7];
    const float* ln_g   = (const float*)d_in[8];
    const float* ln_b   = (const float*)d_in[9];
    float* out = (float*)d_out;

    __nv_bfloat16 *xhi, *xlo, *w1hi, *w1lo, *w2hi, *w2lo, *w3hi, *w3lo, *hnhi, *hnlo;
    float *ih, *gt, *cA, *cB, *pref;
    cudaGetSymbolAddress((void**)&xhi,  g_xhi);
    cudaGetSymbolAddress((void**)&xlo,  g_xlo);
    cudaGetSymbolAddress((void**)&w1hi, g_w1hi);
    cudaGetSymbolAddress((void**)&w1lo, g_w1lo);
    cudaGetSymbolAddress((void**)&w2hi, g_w2hi);
    cudaGetSymbolAddress((void**)&w2lo, g_w2lo);
    cudaGetSymbolAddress((void**)&w3hi, g_w3hi);
    cudaGetSymbolAddress((void**)&w3lo, g_w3lo);
    cudaGetSymbolAddress((void**)&hnhi, g_hnhi);
    cudaGetSymbolAddress((void**)&hnlo, g_hnlo);
    cudaGetSymbolAddress((void**)&ih,   g_ih);
    cudaGetSymbolAddress((void**)&gt,   g_gate);
    cudaGetSymbolAddress((void**)&cA,   g_cA);
    cudaGetSymbolAddress((void**)&cB,   g_cB);
    cudaGetSymbolAddress((void**)&pref, g_pref);

    cudaFuncSetAttribute(gemm_bf16x2,
                         cudaFuncAttributeMaxDynamicSharedMemorySize, DYN_B);

    // splits
    split32<<<(size_t)CM * CD / 4 / 256, 256>>>(x,      xhi,  xlo);
    split32<<<(size_t)CH * CD / 4 / 256, 256>>>(W_ih,   w1hi, w1lo);
    split32<<<(size_t)CH * CD / 4 / 256, 256>>>(W_gate, w2hi, w2lo);
    split32<<<(size_t)CO * CH / 4 / 256, 256>>>(W_out,  w3hi, w3lo);

    // input GEMMs
    dim3 g1(CH / 128, CM / 128);
    gemm_bf16x2<<<g1, 256, DYN_B>>>(xhi, xlo, w1hi, w1lo, nullptr, ih, CM, CH, CD);
    gemm_bf16x2<<<g1, 256, DYN_B>>>(xhi, xlo, w2hi, w2lo, nullptr, gt, CM, CH, CD);

    // fused elementwise + chunked scan
    scan_local<<<(CB * CH * NCHUNK) / 256, 256>>>(ih, gt, b_ih, b_gate, log_a, cA, cB);
    scan_carry<<<(CB * CH) / 256, 256>>>(cA, cB, pref);
    fix_ln<<<CM, 256>>>(gt, ih, pref, ln_g, ln_b, hnhi, hnlo);

    // output GEMM
    dim3 g3(CO / 128, CM / 128);
    gemm_bf16x2<<<g3, 256, DYN_B>>>(hnhi, hnlo, w3hi, w3lo, b_out, out, CM, CO, CH);
}

// round 5
// speedup vs baseline: 2.5901x; 1.0486x over previous
#include <cuda_runtime.h>
#include <cuda_bf16.h>
#include <cstdint>

// Problem constants (fixed shapes from reference)
#define CB 4
#define CT 8192
#define CD 1024
#define CH 1024
#define CO 1024
#define CM (CB*CT)    // 32768 rows
#define NCHUNK 64
#define CHUNK (CT/NCHUNK)   // 128
#define LN_EPS 1e-5f

// ---------------- scratch (device globals; no allocation allowed) -------------
__device__ __nv_bfloat16 g_xhi[(size_t)CM*CD];
__device__ __nv_bfloat16 g_xlo[(size_t)CM*CD];
__device__ __nv_bfloat16 g_w1hi[(size_t)CH*CD], g_w1lo[(size_t)CH*CD];
__device__ __nv_bfloat16 g_w2hi[(size_t)CH*CD], g_w2lo[(size_t)CH*CD];
__device__ __nv_bfloat16 g_w3hi[(size_t)CO*CH], g_w3lo[(size_t)CO*CH];
__device__ float g_ih[(size_t)CM*CH];
__device__ float g_gate[(size_t)CM*CH];
__device__ __nv_bfloat16 g_hnhi[(size_t)CM*CH];
__device__ __nv_bfloat16 g_hnlo[(size_t)CM*CH];
__device__ float g_cA[CB*NCHUNK*CH];
__device__ float g_cB[CB*NCHUNK*CH];
__device__ float g_pref[CB*NCHUNK*CH];

// ------------------------------ helpers ---------------------------------------
__device__ __forceinline__ uint32_t s2u(const void* p) {
    return (uint32_t)__cvta_generic_to_shared(p);
}
__device__ __forceinline__ void cp16(uint32_t s, const void* g) {
    asm volatile("cp.async.cg.shared.global [%0], [%1], 16;" :: "r"(s), "l"(g));
}
#define CP_COMMIT() asm volatile("cp.async.commit_group;" ::: "memory")

__device__ __forceinline__ void ldsm4(uint32_t* r, uint32_t addr) {
    asm volatile("ldmatrix.sync.aligned.m8n8.x4.shared.b16 {%0,%1,%2,%3}, [%4];"
        : "=r"(r[0]), "=r"(r[1]), "=r"(r[2]), "=r"(r[3]) : "r"(addr));
}

#define MMA_BF16(d, a, b) \
    asm volatile("mma.sync.aligned.m16n8k16.row.col.f32.bf16.bf16.f32 " \
        "{%0,%1,%2,%3}, {%4,%5,%6,%7}, {%8,%9}, {%0,%1,%2,%3};" \
        : "+f"(d[0]), "+f"(d[1]), "+f"(d[2]), "+f"(d[3]) \
        : "r"(a[0]), "r"(a[1]), "r"(a[2]), "r"(a[3]), "r"(b[0]), "r"(b[1]))

// ------------------------- fp32 -> bf16 hi/lo split ---------------------------
__global__ __launch_bounds__(256) void split32(
    const float* __restrict__ src,
    __nv_bfloat16* __restrict__ hi, __nv_bfloat16* __restrict__ lo)
{
    size_t i = ((size_t)blockIdx.x * 256 + threadIdx.x) * 4;
    float4 v = *reinterpret_cast<const float4*>(src + i);
    float vv[4] = {v.x, v.y, v.z, v.w};
    __nv_bfloat16 h[4], l[4];
#pragma unroll
    for (int c = 0; c < 4; c++) {
        h[c] = __float2bfloat16(vv[c]);
        l[c] = __float2bfloat16(vv[c] - __bfloat162float(h[c]));
    }
    __nv_bfloat162* ph = reinterpret_cast<__nv_bfloat162*>(hi + i);
    __nv_bfloat162* pl = reinterpret_cast<__nv_bfloat162*>(lo + i);
    ph[0] = __nv_bfloat162(h[0], h[1]);
    ph[1] = __nv_bfloat162(h[2], h[3]);
    pl[0] = __nv_bfloat162(l[0], l[1]);
    pl[1] = __nv_bfloat162(l[2], l[3]);
}

// ---------------------- bf16-split tensor-core GEMM ---------------------------
// Dual-output: gridDim.x = 16 -> bx<8 uses (B1,C1,bias1), else (B2,C2,bias2).
// (For single-output GEMMs, pass identical sets and gridDim.x = 8.)
// C[m][n] = sum_k A[m][k]*B[n][k] (+bias[n]); 128x128 tile, BK=64, 3-stage
// cp.async with ONE __syncthreads per iteration, ldmatrix.x4, XOR swizzle.

#define PART_B 16384               // 128 rows x 128B (64 bf16)
#define STAGE_B (4*PART_B)         // Ahi|Alo|Bhi|Blo = 64KB per stage
#define NSTAGE 3
#define DYN_B (NSTAGE*STAGE_B + 1024)

__global__ __launch_bounds__(256, 1) void gemm_bf16x2(
    const __nv_bfloat16* __restrict__ Ahi, const __nv_bfloat16* __restrict__ Alo,
    const __nv_bfloat16* __restrict__ B1hi, const __nv_bfloat16* __restrict__ B1lo,
    const __nv_bfloat16* __restrict__ B2hi, const __nv_bfloat16* __restrict__ B2lo,
    const float* __restrict__ bias1, const float* __restrict__ bias2,
    float* __restrict__ C1, float* __restrict__ C2,
    int M, int N, int K)
{
    extern __shared__ char dyn[];
    const uint32_t tile = (s2u(dyn) + 127u) & ~127u;

    const int tid = threadIdx.x;
    const int bx = blockIdx.x;
    const bool first = bx < 8;
    const __nv_bfloat16* Bhi = first ? B1hi : B2hi;
    const __nv_bfloat16* Blo = first ? B1lo : B2lo;
    const float* bias = first ? bias1 : bias2;
    float* C = first ? C1 : C2;
    const int m0 = blockIdx.y * 128;
    const int n0 = (bx & 7) * 128;

    const int wid = tid >> 5, lane = tid & 31;
    const int wm = wid >> 2;       // 0..1
    const int wn = wid & 3;        // 0..3

    const __nv_bfloat16* srcs[4] = {
        Ahi + (size_t)m0 * K, Alo + (size_t)m0 * K,
        Bhi + (size_t)n0 * K, Blo + (size_t)n0 * K };

    // cp.async: thread t -> row r = t>>1, chunks (t&1)*4 .. +3 (16B each)
    const int lr = tid >> 1;
    const int lc0 = (tid & 1) * 4;
    const int lsw = lr & 7;

    auto issue = [&](int s) {
        uint32_t sb = tile + (uint32_t)(s % NSTAGE) * STAGE_B;
        int k0 = s * 64;
#pragma unroll
        for (int p = 0; p < 4; p++) {
            const __nv_bfloat16* g = srcs[p] + (size_t)lr * K + k0 + lc0 * 8;
            uint32_t base = sb + p * PART_B + lr * 128;
#pragma unroll
            for (int c = 0; c < 4; c++)
                cp16(base + (((lc0 + c) ^ lsw) << 4), g + c * 8);
        }
        CP_COMMIT();
    };

    // ldmatrix address precomputation
    const int arow = wm * 64 + (lane & 15);
    const int ahalf = lane >> 4;
    const int asw = arow & 7;
    const int brow = wn * 32 + ((lane >> 4) << 3) + (lane & 7);
    const int bhalf = (lane >> 3) & 1;
    const int bsw = brow & 7;

    float acc[4][4][4];
#pragma unroll
    for (int i = 0; i < 4; i++)
#pragma unroll
        for (int j = 0; j < 4; j++)
#pragma unroll
            for (int c = 0; c < 4; c++) acc[i][j][c] = 0.f;

    issue(0); issue(1);

    const int NIT = K / 64;
    for (int it = 0; it < NIT; ++it) {
        if (it + 1 < NIT) asm volatile("cp.async.wait_group 1;" ::: "memory");
        else              asm volatile("cp.async.wait_group 0;" ::: "memory");
        __syncthreads();
        // slot (it+2)%3 == (it-1)%3: consumed last iter, free after this sync
        if (it + 2 < NIT) issue(it + 2);

        uint32_t sb = tile + (uint32_t)(it % NSTAGE) * STAGE_B;
        uint32_t aAhi = sb              + arow * 128;
        uint32_t aAlo = sb +     PART_B + arow * 128;
        uint32_t aBhi = sb + 2 * PART_B + brow * 128;
        uint32_t aBlo = sb + 3 * PART_B + brow * 128;

#pragma unroll
        for (int ks = 0; ks < 4; ks++) {
            const int ac = (2 * ks + ahalf) ^ asw;
            const int bc = (2 * ks + bhalf) ^ bsw;
            uint32_t ahi[4][4], alo[4][4], bhi[4][2], blo[4][2];
#pragma unroll
            for (int i = 0; i < 4; i++) {
                ldsm4(ahi[i], aAhi + i * (16 * 128) + (ac << 4));
                ldsm4(alo[i], aAlo + i * (16 * 128) + (ac << 4));
            }
#pragma unroll
            for (int q = 0; q < 2; q++) {
                uint32_t rb[4];
                ldsm4(rb, aBhi + q * (16 * 128) + (bc << 4));
                bhi[q*2+0][0] = rb[0]; bhi[q*2+0][1] = rb[1];
                bhi[q*2+1][0] = rb[2]; bhi[q*2+1][1] = rb[3];
                ldsm4(rb, aBlo + q * (16 * 128) + (bc << 4));
                blo[q*2+0][0] = rb[0]; blo[q*2+0][1] = rb[1];
                blo[q*2+1][0] = rb[2]; blo[q*2+1][1] = rb[3];
            }
#pragma unroll
            for (int i = 0; i < 4; i++)
#pragma unroll
                for (int j = 0; j < 4; j++) {
                    MMA_BF16(acc[i][j], ahi[i], bhi[j]);
                    MMA_BF16(acc[i][j], ahi[i], blo[j]);
                    MMA_BF16(acc[i][j], alo[i], bhi[j]);
                }
        }
    }

    // epilogue
    const int g = lane >> 2, tq = lane & 3;
#pragma unroll
    for (int i = 0; i < 4; i++) {
        const int m = m0 + wm * 64 + i * 16 + g;
#pragma unroll
        for (int j = 0; j < 4; j++) {
            const int n = n0 + wn * 32 + j * 8 + tq * 2;
            float b0 = 0.f, b1 = 0.f;
            if (bias) { b0 = bias[n]; b1 = bias[n + 1]; }
            float2 v0 = { acc[i][j][0] + b0, acc[i][j][1] + b1 };
            float2 v1 = { acc[i][j][2] + b0, acc[i][j][3] + b1 };
            *reinterpret_cast<float2*>(C + (size_t)m * N + n)       = v0;
            *reinterpret_cast<float2*>(C + (size_t)(m + 8) * N + n) = v1;
        }
    }
}

// ---- pass A (fused): gate/alpha/beta from raw GEMM outputs + local scan ------
__global__ __launch_bounds__(256) void scan_local(
    float* __restrict__ ih_arr, float* __restrict__ gate_arr,
    const float* __restrict__ b_ih, const float* __restrict__ b_g,
    const float* __restrict__ log_a,
    float* __restrict__ cA, float* __restrict__ cB)
{
    int idx = blockIdx.x * blockDim.x + threadIdx.x;  // B*H*NCHUNK threads
    int h = idx % CH;
    int c = (idx / CH) % NCHUNK;
    int b = idx / (CH * NCHUNK);
    const float bg = b_g[h], bi = b_ih[h], ea = __expf(log_a[h]);
    size_t base = ((size_t)b * CT + (size_t)c * CHUNK) * CH + h;
    float p = 1.f, hl = 0.f;
#pragma unroll 8
    for (int t = 0; t < CHUNK; t++) {
        size_t o = base + (size_t)t * CH;
        float graw = gate_arr[o];
        float iraw = ih_arr[o];
        float gate = 1.f / (1.f + __expf(-(graw + bg)));
        float beta = gate * (iraw + bi);
        float a = (1.f - gate) * ea;
        hl = fmaf(a, hl, beta);
        p *= a;
        gate_arr[o] = p;
        ih_arr[o] = hl;
    }
    cA[((size_t)b * NCHUNK + c) * CH + h] = p;
    cB[((size_t)b * NCHUNK + c) * CH + h] = hl;
}

// ---------------- pass B: scan across chunk summaries per (b,h) ---------------
__global__ __launch_bounds__(256) void scan_carry(
    const float* __restrict__ cA, const float* __restrict__ cB,
    float* __restrict__ pref)
{
    int idx = blockIdx.x * blockDim.x + threadIdx.x;  // B*H threads
    int h = idx % CH;
    int b = idx / CH;
    float run = 0.f;
#pragma unroll
    for (int c = 0; c < NCHUNK; c++) {
        size_t o = ((size_t)b * NCHUNK + c) * CH + h;
        pref[o] = run;
        run = fmaf(cA[o], run, cB[o]);
    }
}

// ------- pass C: fixup h = h_local + P*carry, fused LayerNorm -> bf16 hi/lo ----
__global__ __launch_bounds__(256) void fix_ln(
    const float* __restrict__ P, const float* __restrict__ HL,
    const float* __restrict__ pref,
    const float* __restrict__ lng, const float* __restrict__ lnb,
    __nv_bfloat16* __restrict__ hnhi, __nv_bfloat16* __restrict__ hnlo)
{
    __shared__ float sred[16];
    const int row = blockIdx.x;
    const int b = row / CT;
    const int t = row % CT;
    const int c = t / CHUNK;
    const size_t base = (size_t)row * CH;
    const float* prow = pref + ((size_t)b * NCHUNK + c) * CH;
    const int h = threadIdx.x * 4;

    float4 p4  = *reinterpret_cast<const float4*>(P + base + h);
    float4 hl4 = *reinterpret_cast<const float4*>(HL + base + h);
    float4 pr4 = *reinterpret_cast<const float4*>(prow + h);
    float v[4];
    v[0] = fmaf(p4.x, pr4.x, hl4.x);
    v[1] = fmaf(p4.y, pr4.y, hl4.y);
    v[2] = fmaf(p4.z, pr4.z, hl4.z);
    v[3] = fmaf(p4.w, pr4.w, hl4.w);

    float s = v[0] + v[1] + v[2] + v[3];
    float ss = v[0]*v[0] + v[1]*v[1] + v[2]*v[2] + v[3]*v[3];
#pragma unroll
    for (int off = 16; off > 0; off >>= 1) {
        s  += __shfl_xor_sync(0xffffffffu, s,  off);
        ss += __shfl_xor_sync(0xffffffffu, ss, off);
    }
    const int warp = threadIdx.x >> 5, lane = threadIdx.x & 31;
    if (lane == 0) { sred[warp] = s; sred[8 + warp] = ss; }
    __syncthreads();
    if (threadIdx.x < 32) {
        float a  = (lane < 8) ? sred[lane]     : 0.f;
        float b2 = (lane < 8) ? sred[8 + lane] : 0.f;
#pragma unroll
        for (int off = 4; off > 0; off >>= 1) {
            a  += __shfl_xor_sync(0xffffffffu, a,  off);
            b2 += __shfl_xor_sync(0xffffffffu, b2, off);
        }
        if (lane == 0) { sred[0] = a; sred[1] = b2; }
    }
    __syncthreads();
    const float mu  = sred[0] * (1.f / CH);
    const float var = sred[1] * (1.f / CH) - mu * mu;
    const float inv = rsqrtf(var + LN_EPS);

    float4 g4 = *reinterpret_cast<const float4*>(lng + h);
    float4 b4 = *reinterpret_cast<const float4*>(lnb + h);
    float o[4];
    o[0] = (v[0] - mu) * inv * g4.x + b4.x;
    o[1] = (v[1] - mu) * inv * g4.y + b4.y;
    o[2] = (v[2] - mu) * inv * g4.z + b4.z;
    o[3] = (v[3] - mu) * inv * g4.w + b4.w;

    __nv_bfloat16 hi[4], lo[4];
#pragma unroll
    for (int k = 0; k < 4; k++) {
        hi[k] = __float2bfloat16(o[k]);
        lo[k] = __float2bfloat16(o[k] - __bfloat162float(hi[k]));
    }
    __nv_bfloat162* phh = reinterpret_cast<__nv_bfloat162*>(hnhi + base + h);
    __nv_bfloat162* pll = reinterpret_cast<__nv_bfloat162*>(hnlo + base + h);
    phh[0] = __nv_bfloat162(hi[0], hi[1]);
    phh[1] = __nv_bfloat162(hi[2], hi[3]);
    pll[0] = __nv_bfloat162(lo[0], lo[1]);
    pll[1] = __nv_bfloat162(lo[2], lo[3]);
}

// --------------------------------- launcher ----------------------------------
extern "C" void kernel_launch(void* const* d_in, const int* in_sizes, int n_in,
                              void* d_out, int out_size)
{
    const float* x      = (const float*)d_in[0];
    const float* W_ih   = (const float*)d_in[1];
    const float* b_ih   = (const float*)d_in[2];
    const float* log_a  = (const float*)d_in[3];
    const float* W_gate = (const float*)d_in[4];
    const float* b_gate = (const float*)d_in[5];
    const float* W_out  = (const float*)d_in[6];
    const float* b_out  = (const float*)d_in[7];
    const float* ln_g   = (const float*)d_in[8];
    const float* ln_b   = (const float*)d_in[9];
    float* out = (float*)d_out;

    __nv_bfloat16 *xhi, *xlo, *w1hi, *w1lo, *w2hi, *w2lo, *w3hi, *w3lo, *hnhi, *hnlo;
    float *ih, *gt, *cA, *cB, *pref;
    cudaGetSymbolAddress((void**)&xhi,  g_xhi);
    cudaGetSymbolAddress((void**)&xlo,  g_xlo);
    cudaGetSymbolAddress((void**)&w1hi, g_w1hi);
    cudaGetSymbolAddress((void**)&w1lo, g_w1lo);
    cudaGetSymbolAddress((void**)&w2hi, g_w2hi);
    cudaGetSymbolAddress((void**)&w2lo, g_w2lo);
    cudaGetSymbolAddress((void**)&w3hi, g_w3hi);
    cudaGetSymbolAddress((void**)&w3lo, g_w3lo);
    cudaGetSymbolAddress((void**)&hnhi, g_hnhi);
    cudaGetSymbolAddress((void**)&hnlo, g_hnlo);
    cudaGetSymbolAddress((void**)&ih,   g_ih);
    cudaGetSymbolAddress((void**)&gt,   g_gate);
    cudaGetSymbolAddress((void**)&cA,   g_cA);
    cudaGetSymbolAddress((void**)&cB,   g_cB);
    cudaGetSymbolAddress((void**)&pref, g_pref);

    cudaFuncSetAttribute(gemm_bf16x2,
                         cudaFuncAttributeMaxDynamicSharedMemorySize, DYN_B);

    // splits
    split32<<<(size_t)CM * CD / 4 / 256, 256>>>(x,      xhi,  xlo);
    split32<<<(size_t)CH * CD / 4 / 256, 256>>>(W_ih,   w1hi, w1lo);
    split32<<<(size_t)CH * CD / 4 / 256, 256>>>(W_gate, w2hi, w2lo);
    split32<<<(size_t)CO * CH / 4 / 256, 256>>>(W_out,  w3hi, w3lo);

    // fused dual input GEMM: bx<8 -> (W_ih -> ih), bx>=8 -> (W_gate -> gt)
    gemm_bf16x2<<<dim3(16, CM / 128), 256, DYN_B>>>(
        xhi, xlo, w1hi, w1lo, w2hi, w2lo, nullptr, nullptr, ih, gt, CM, CH, CD);

    // fused elementwise + chunked scan
    scan_local<<<(CB * CH * NCHUNK) / 256, 256>>>(ih, gt, b_ih, b_gate, log_a, cA, cB);
    scan_carry<<<(CB * CH) / 256, 256>>>(cA, cB, pref);
    fix_ln<<<CM, 256>>>(gt, ih, pref, ln_g, ln_b, hnhi, hnlo);

    // output GEMM (single-output: both sets identical, grid.x = 8)
    gemm_bf16x2<<<dim3(8, CM / 128), 256, DYN_B>>>(
        hnhi, hnlo, w3hi, w3lo, w3hi, w3lo, b_out, b_out, out, out, CM, CO, CH);
}